// round 1
// baseline (speedup 1.0000x reference)
#include <cuda_runtime.h>

#define BB 16
#define NN 10000
#define DD 128
#define OO 64
#define KK 3
#define EE 160000
#define BO (BB*OO)   /* 1024 */
#define KO (KK*OO)   /* 192  */
#define NPB 4        /* nodes per GEMM block */

// ---------------- scratch (device globals; no runtime allocation) -----------
__device__ float g_pre[KK][NN*BO];       // 122.88 MB: pre[i][n][b][o]
__device__ int   g_rowstart[KK][NN+1];
__device__ int   g_cursor[KK][NN];
__device__ int   g_ecol[KK][EE];
__device__ float g_eval[KK][EE];

// ---------------- CSR build --------------------------------------------------
__global__ void k_zero_counts() {
    int idx = blockIdx.x * blockDim.x + threadIdx.x;
    if (idx < KK * NN) ((int*)g_cursor)[idx] = 0;
}

__global__ void k_hist(const int* __restrict__ rows) {
    int idx = blockIdx.x * blockDim.x + threadIdx.x;
    if (idx < KK * EE) {
        int i = idx / EE;
        atomicAdd(&g_cursor[i][rows[idx]], 1);
    }
}

// One block per support: exclusive scan of counts -> rowstart, cursor
__global__ void k_scan() {
    int i = blockIdx.x;
    int t = threadIdx.x;
    __shared__ int sh[1024];
    __shared__ int carry;
    if (t == 0) carry = 0;
    __syncthreads();
    const int NT = (NN + 1023) / 1024;
    for (int tile = 0; tile < NT; tile++) {
        int idx = tile * 1024 + t;
        int v = (idx < NN) ? g_cursor[i][idx] : 0;
        sh[t] = v;
        __syncthreads();
        for (int off = 1; off < 1024; off <<= 1) {
            int a = (t >= off) ? sh[t - off] : 0;
            __syncthreads();
            sh[t] += a;
            __syncthreads();
        }
        int excl = sh[t] - v + carry;
        if (idx < NN) {
            g_rowstart[i][idx] = excl;
            g_cursor[i][idx]   = excl;   // becomes scatter cursor
        }
        __syncthreads();
        if (t == 0) carry += sh[1023];
        __syncthreads();
    }
    if (t == 0) g_rowstart[i][NN] = carry;
}

__global__ void k_scatter(const float* __restrict__ vals,
                          const int* __restrict__ rows,
                          const int* __restrict__ cols) {
    int idx = blockIdx.x * blockDim.x + threadIdx.x;
    if (idx < KK * EE) {
        int i = idx / EE;
        int r = rows[idx];
        int pos = atomicAdd(&g_cursor[i][r], 1);
        g_ecol[i][pos] = cols[idx];
        g_eval[i][pos] = vals[idx];
    }
}

// ---------------- dense transform: pre[i][n][b][o] = sum_d x[b][n][d]*W[i][d][o]
__global__ void __launch_bounds__(256) k_gemm(const float* __restrict__ x,
                                              const float* __restrict__ W) {
    __shared__ float xs[NPB][BB][DD];     // 32 KB
    int n0 = blockIdx.x * NPB;
    int t  = threadIdx.x;

    // stage x for NPB nodes, all 16 batches (coalesced 128-float rows)
    for (int idx = t; idx < NPB * BB * DD; idx += 256) {
        int node = idx >> 11;             // /2048
        int rem  = idx & 2047;
        int b    = rem >> 7;
        int d    = rem & 127;
        xs[node][b][d] = x[(size_t)b * (NN * DD) + (size_t)(n0 + node) * DD + d];
    }
    __syncthreads();

    int o  = t & 63;       // fixed output column per thread
    int b0 = t >> 6;       // batches b0, b0+4, b0+8, b0+12

    float acc[KK][NPB][4];
#pragma unroll
    for (int i = 0; i < KK; i++)
#pragma unroll
        for (int nn = 0; nn < NPB; nn++)
#pragma unroll
            for (int j = 0; j < 4; j++) acc[i][nn][j] = 0.0f;

    const float* Wp = W + o;
    for (int d = 0; d < DD; d++) {
        float xv[NPB][4];
#pragma unroll
        for (int nn = 0; nn < NPB; nn++)
#pragma unroll
            for (int j = 0; j < 4; j++)
                xv[nn][j] = xs[nn][b0 + 4 * j][d];   // warp-broadcast LDS
#pragma unroll
        for (int i = 0; i < KK; i++) {
            float w = __ldg(&Wp[(i * DD + d) * OO]); // L1-resident (96 KB total)
#pragma unroll
            for (int nn = 0; nn < NPB; nn++)
#pragma unroll
                for (int j = 0; j < 4; j++)
                    acc[i][nn][j] += xv[nn][j] * w;
        }
    }

#pragma unroll
    for (int i = 0; i < KK; i++)
#pragma unroll
        for (int nn = 0; nn < NPB; nn++)
#pragma unroll
            for (int j = 0; j < 4; j++)
                g_pre[i][(size_t)(n0 + nn) * BO + (b0 + 4 * j) * OO + o] = acc[i][nn][j];
}

// ---------------- SpMM gather: out[b][r][i*O+o] = sum_e val * pre[i][c][b][o]
__global__ void __launch_bounds__(256) k_spmm(float* __restrict__ out) {
    int r = blockIdx.x;
    int i = blockIdx.y;
    int t = threadIdx.x;
    __shared__ int   scol[256];
    __shared__ float sval[256];

    int start = g_rowstart[i][r];
    int end   = g_rowstart[i][r + 1];

    float acc[4] = {0.f, 0.f, 0.f, 0.f};
    const float* pre = g_pre[i];

    for (int base = start; base < end; base += 256) {
        int cnt = min(256, end - base);
        if (t < cnt) {
            scol[t] = g_ecol[i][base + t];
            sval[t] = g_eval[i][base + t];
        }
        __syncthreads();
        for (int e = 0; e < cnt; e++) {
            int   c = scol[e];
            float v = sval[e];
            const float* p = pre + (size_t)c * BO + t;
            acc[0] += v * p[0];
            acc[1] += v * p[256];
            acc[2] += v * p[512];
            acc[3] += v * p[768];
        }
        __syncthreads();
    }

#pragma unroll
    for (int j = 0; j < 4; j++) {
        int slot = t + 256 * j;
        int b = slot >> 6;
        int o = slot & 63;
        out[(size_t)b * (NN * KO) + (size_t)r * KO + i * OO + o] = acc[j];
    }
}

// ---------------- launch -----------------------------------------------------
extern "C" void kernel_launch(void* const* d_in, const int* in_sizes, int n_in,
                              void* d_out, int out_size) {
    const float* x        = (const float*)d_in[0];
    const float* W        = (const float*)d_in[1];
    const float* sup_vals = (const float*)d_in[2];
    const int*   sup_row  = (const int*)d_in[3];
    const int*   sup_col  = (const int*)d_in[4];
    float* out = (float*)d_out;

    k_zero_counts<<<(KK * NN + 255) / 256, 256>>>();
    k_hist<<<(KK * EE + 255) / 256, 256>>>(sup_row);
    k_scan<<<KK, 1024>>>();
    k_scatter<<<(KK * EE + 255) / 256, 256>>>(sup_vals, sup_row, sup_col);
    k_gemm<<<NN / NPB, 256>>>(x, W);
    k_spmm<<<dim3(NN, KK), 256>>>(out);
}

// round 2
// speedup vs baseline: 1.1422x; 1.1422x over previous
#include <cuda_runtime.h>

#define BB 16
#define NN 10000
#define DD 128
#define OO 64
#define KK 3
#define EE 160000
#define BO (BB*OO)   /* 1024 */
#define KO (KK*OO)   /* 192  */
#define NPB 4        /* nodes per GEMM block */

// ---------------- scratch (device globals; no runtime allocation) -----------
__device__ __align__(16) float g_pre[KK][NN*BO];   // 122.88 MB: pre[i][n][b][o]
__device__ int   g_rowstart[KK][NN+1];
__device__ int   g_cursor[KK][NN];
__device__ int   g_ecol[KK][EE];
__device__ float g_eval[KK][EE];

// ---------------- f32x2 packed-FMA helpers (sm_103a fma pipe, 2 MACs/instr) --
__device__ __forceinline__ unsigned long long pk2(float a, float b) {
    unsigned long long r;
    asm("mov.b64 %0, {%1, %2};" : "=l"(r) : "f"(a), "f"(b));
    return r;
}
__device__ __forceinline__ void fma2(unsigned long long& d,
                                     unsigned long long a, unsigned long long b) {
    asm("fma.rn.f32x2 %0, %1, %2, %0;" : "+l"(d) : "l"(a), "l"(b));
}
__device__ __forceinline__ void unpk2(unsigned long long v, float& a, float& b) {
    asm("mov.b64 {%0, %1}, %2;" : "=f"(a), "=f"(b) : "l"(v));
}

// ---------------- CSR build --------------------------------------------------
__global__ void k_zero_counts() {
    int idx = blockIdx.x * blockDim.x + threadIdx.x;
    if (idx < KK * NN) ((int*)g_cursor)[idx] = 0;
}

__global__ void k_hist(const int* __restrict__ rows) {
    int idx = blockIdx.x * blockDim.x + threadIdx.x;
    if (idx < KK * EE) {
        int i = idx / EE;
        atomicAdd(&g_cursor[i][rows[idx]], 1);
    }
}

// One block per support: exclusive scan of counts -> rowstart, cursor
__global__ void k_scan() {
    int i = blockIdx.x;
    int t = threadIdx.x;
    __shared__ int sh[1024];
    __shared__ int carry;
    if (t == 0) carry = 0;
    __syncthreads();
    const int NT = (NN + 1023) / 1024;
    for (int tile = 0; tile < NT; tile++) {
        int idx = tile * 1024 + t;
        int v = (idx < NN) ? g_cursor[i][idx] : 0;
        sh[t] = v;
        __syncthreads();
        for (int off = 1; off < 1024; off <<= 1) {
            int a = (t >= off) ? sh[t - off] : 0;
            __syncthreads();
            sh[t] += a;
            __syncthreads();
        }
        int excl = sh[t] - v + carry;
        if (idx < NN) {
            g_rowstart[i][idx] = excl;
            g_cursor[i][idx]   = excl;   // becomes scatter cursor
        }
        __syncthreads();
        if (t == 0) carry += sh[1023];
        __syncthreads();
    }
    if (t == 0) g_rowstart[i][NN] = carry;
}

__global__ void k_scatter(const float* __restrict__ vals,
                          const int* __restrict__ rows,
                          const int* __restrict__ cols) {
    int idx = blockIdx.x * blockDim.x + threadIdx.x;
    if (idx < KK * EE) {
        int i = idx / EE;
        int r = rows[idx];
        int pos = atomicAdd(&g_cursor[i][r], 1);
        g_ecol[i][pos] = cols[idx];
        g_eval[i][pos] = vals[idx];
    }
}

// ---------------- dense transform: pre[i][n][b][o] = sum_d x[b][n][d]*W[i][d][o]
// Thread mapping: b = t&15 (fixed batch), o = 4*(t>>4) (4 consecutive outputs).
// -> scalar broadcast LDS for x, LDG.128 for W, FFMA2 accumulation, STG.128 out.
__global__ void __launch_bounds__(256) k_gemm(const float* __restrict__ x,
                                              const float* __restrict__ W) {
    __shared__ float xs[NPB][DD][BB + 1];   // [4][128][17] = 34.8 KB, pad kills conflicts
    int n0 = blockIdx.x * NPB;
    int t  = threadIdx.x;

    // stage x: float4 gmem reads (coalesced over d4), scalar transposed STS
    for (int idx = t; idx < NPB * BB * (DD / 4); idx += 256) {
        int d4   = idx & 31;
        int b    = (idx >> 5) & 15;
        int node = idx >> 9;
        float4 v = *(const float4*)&x[((size_t)b * NN + (n0 + node)) * DD + 4 * d4];
        xs[node][4 * d4 + 0][b] = v.x;
        xs[node][4 * d4 + 1][b] = v.y;
        xs[node][4 * d4 + 2][b] = v.z;
        xs[node][4 * d4 + 3][b] = v.w;
    }
    __syncthreads();

    int b = t & 15;
    int o = 4 * (t >> 4);

    unsigned long long acc[KK][NPB][2];
#pragma unroll
    for (int i = 0; i < KK; i++)
#pragma unroll
        for (int nn = 0; nn < NPB; nn++) {
            acc[i][nn][0] = 0ull;
            acc[i][nn][1] = 0ull;
        }

#pragma unroll 2
    for (int d = 0; d < DD; d++) {
        unsigned long long xp[NPB];
#pragma unroll
        for (int nn = 0; nn < NPB; nn++) {
            float xv = xs[nn][d][b];        // broadcast LDS
            xp[nn] = pk2(xv, xv);
        }
#pragma unroll
        for (int i = 0; i < KK; i++) {
            float4 w = *(const float4*)&W[(size_t)(i * DD + d) * OO + o];  // L1-hit
            unsigned long long w01 = pk2(w.x, w.y);
            unsigned long long w23 = pk2(w.z, w.w);
#pragma unroll
            for (int nn = 0; nn < NPB; nn++) {
                fma2(acc[i][nn][0], xp[nn], w01);
                fma2(acc[i][nn][1], xp[nn], w23);
            }
        }
    }

#pragma unroll
    for (int i = 0; i < KK; i++)
#pragma unroll
        for (int nn = 0; nn < NPB; nn++) {
            float4 r;
            unpk2(acc[i][nn][0], r.x, r.y);
            unpk2(acc[i][nn][1], r.z, r.w);
            *(float4*)&g_pre[i][(size_t)(n0 + nn) * BO + b * OO + o] = r;  // STG.128
        }
}

// ---------------- SpMM gather: out[b][r][i*O+o] = sum_e val * pre[i][c][b][o]
// Thread t owns float4 at offset 4t of the 1024-float row: 1 LDG.128 + 2 FFMA2 / edge.
__global__ void __launch_bounds__(256) k_spmm(float* __restrict__ out) {
    int r = blockIdx.x;
    int i = blockIdx.y;
    int t = threadIdx.x;
    __shared__ int   scol[256];
    __shared__ float sval[256];

    int start = g_rowstart[i][r];
    int end   = g_rowstart[i][r + 1];

    unsigned long long acc0 = 0ull, acc1 = 0ull;
    const float* pre = g_pre[i];

    for (int base = start; base < end; base += 256) {
        int cnt = min(256, end - base);
        if (t < cnt) {
            scol[t] = g_ecol[i][base + t];
            sval[t] = g_eval[i][base + t];
        }
        __syncthreads();
#pragma unroll 4
        for (int e = 0; e < cnt; e++) {
            int   c = scol[e];
            float v = sval[e];
            ulonglong2 p = *(const ulonglong2*)(pre + (size_t)c * BO + 4 * t);  // LDG.128
            unsigned long long vv = pk2(v, v);
            fma2(acc0, vv, p.x);
            fma2(acc1, vv, p.y);
        }
        __syncthreads();
    }

    int b = t >> 4;
    int o = 4 * (t & 15);
    float4 res;
    unpk2(acc0, res.x, res.y);
    unpk2(acc1, res.z, res.w);
    *(float4*)&out[(size_t)b * (NN * KO) + (size_t)r * KO + i * OO + o] = res;  // STG.128
}

// ---------------- launch -----------------------------------------------------
extern "C" void kernel_launch(void* const* d_in, const int* in_sizes, int n_in,
                              void* d_out, int out_size) {
    const float* x        = (const float*)d_in[0];
    const float* W        = (const float*)d_in[1];
    const float* sup_vals = (const float*)d_in[2];
    const int*   sup_row  = (const int*)d_in[3];
    const int*   sup_col  = (const int*)d_in[4];
    float* out = (float*)d_out;

    k_zero_counts<<<(KK * NN + 255) / 256, 256>>>();
    k_hist<<<(KK * EE + 255) / 256, 256>>>(sup_row);
    k_scan<<<KK, 1024>>>();
    k_scatter<<<(KK * EE + 255) / 256, 256>>>(sup_vals, sup_row, sup_col);
    k_gemm<<<NN / NPB, 256>>>(x, W);
    k_spmm<<<dim3(NN, KK), 256>>>(out);
}